// round 13
// baseline (speedup 1.0000x reference)
#include <cuda_runtime.h>
#include <cuda_bf16.h>
#include <cuda_fp16.h>
#include <math.h>
#include <stdint.h>

// Problem constants: B=8, N=1024, Fin=512, Fout=512, H=8, dh=64
#define BATCH 8
#define NN    1024
#define FIN   512
#define FOUT  512
#define HEADS 8
#define DH    64
#define ALPHA_LR 0.2f

// ---------------- device scratch ----------------
__device__ __nv_bfloat16 g_xh[BATCH * NN * FIN];
__device__ __nv_bfloat16 g_xl[BATCH * NN * FIN];
__device__ __nv_bfloat16 g_wh[FIN * FOUT];
__device__ __nv_bfloat16 g_wl[FIN * FOUT];
__device__ __half        g_hh[BATCH * NN * FOUT];    // h (fp16)
__device__ float         g_sdst[BATCH * HEADS * NN];
__device__ __half        g_f1[BATCH * HEADS * NN];   // exp(ss) fp16
__device__ __half        g_f2[BATCH * HEADS * NN];   // exp(0.2*ss) fp16
__device__ unsigned      g_adjbits[BATCH * NN * (NN / 32)];  // nibble-permuted

// ---------------- PTX helpers ----------------
static __device__ __forceinline__ uint32_t smem_u32(const void* p) {
    return (uint32_t)__cvta_generic_to_shared(p);
}
static __device__ __forceinline__ void ldsm_x4(uint32_t* r, uint32_t a) {
    asm volatile("ldmatrix.sync.aligned.m8n8.x4.shared.b16 {%0,%1,%2,%3}, [%4];"
        : "=r"(r[0]), "=r"(r[1]), "=r"(r[2]), "=r"(r[3]) : "r"(a));
}
static __device__ __forceinline__ void ldsm_x4_t(uint32_t* r, uint32_t a) {
    asm volatile("ldmatrix.sync.aligned.m8n8.x4.trans.shared.b16 {%0,%1,%2,%3}, [%4];"
        : "=r"(r[0]), "=r"(r[1]), "=r"(r[2]), "=r"(r[3]) : "r"(a));
}
// bf16 MMA (GEMM)
static __device__ __forceinline__ void mma16816(float* d, const uint32_t* a,
                                                uint32_t b0, uint32_t b1) {
    asm volatile(
        "mma.sync.aligned.m16n8k16.row.col.f32.bf16.bf16.f32 "
        "{%0,%1,%2,%3}, {%4,%5,%6,%7}, {%8,%9}, {%0,%1,%2,%3};"
        : "+f"(d[0]), "+f"(d[1]), "+f"(d[2]), "+f"(d[3])
        : "r"(a[0]), "r"(a[1]), "r"(a[2]), "r"(a[3]), "r"(b0), "r"(b1));
}
// fp16 MMA (attention P*V)
static __device__ __forceinline__ void mma16816h(float* d, const uint32_t* a,
                                                 uint32_t b0, uint32_t b1) {
    asm volatile(
        "mma.sync.aligned.m16n8k16.row.col.f32.f16.f16.f32 "
        "{%0,%1,%2,%3}, {%4,%5,%6,%7}, {%8,%9}, {%0,%1,%2,%3};"
        : "+f"(d[0]), "+f"(d[1]), "+f"(d[2]), "+f"(d[3])
        : "r"(a[0]), "r"(a[1]), "r"(a[2]), "r"(a[3]), "r"(b0), "r"(b1));
}
static __device__ __forceinline__ void cp16(uint32_t dst, const void* src) {
    asm volatile("cp.async.cg.shared.global [%0], [%1], 16;"
        :: "r"(dst), "l"(src) : "memory");
}
static __device__ __forceinline__ void cp8(uint32_t dst, const void* src) {
    asm volatile("cp.async.ca.shared.global [%0], [%1], 8;"
        :: "r"(dst), "l"(src) : "memory");
}
#define CP_COMMIT() asm volatile("cp.async.commit_group;" ::: "memory")
#define CP_WAIT(n)  asm volatile("cp.async.wait_group %0;" :: "n"(n) : "memory")

// packed p-pair: p = max(E1*F1, E2*F2) * mask   (exp(leakyrelu) identity)
static __device__ __forceinline__ uint32_t ppair(uint32_t f1p, uint32_t f2p,
                                                 __half2 E1, __half2 E2,
                                                 uint32_t mk) {
    __half2 a = __hmul2(E1, *(__half2*)&f1p);
    __half2 b = __hmul2(E2, *(__half2*)&f2p);
    __half2 p = __hmul2(__hmax2(a, b), *(__half2*)&mk);
    return *(uint32_t*)&p;
}
#define ONESH2 0x3C003C00u

// nibble permutation: nibble q of each 16-bit half holds bits {2q,2q+1,2q+8,2q+9}
static __device__ __forceinline__ uint32_t permute_mask(uint32_t m) {
    return (m & 0x00030003u)
         | ((m & 0x000C000Cu) << 2)
         | ((m & 0x00300030u) << 4)
         | ((m & 0x00C000C0u) << 6)
         | ((m & 0x03000300u) >> 6)
         | ((m & 0x0C000C00u) >> 4)
         | ((m & 0x30003000u) >> 2)
         |  (m & 0xC000C000u);
}

// ---------------------------------------------------------------------------
// C0: split X and W into bf16 hi/lo
// ---------------------------------------------------------------------------
__global__ __launch_bounds__(256) void conv_xw(const float* __restrict__ X,
                                               const float* __restrict__ W)
{
    int idx = blockIdx.x * 256 + threadIdx.x;
    const int NX = BATCH * NN * FIN;
    if (idx < NX) {
        float v = X[idx];
        __nv_bfloat16 hi = __float2bfloat16_rn(v);
        g_xh[idx] = hi;
        g_xl[idx] = __float2bfloat16_rn(v - __bfloat162float(hi));
    } else {
        int wi = idx - NX;
        if (wi < FIN * FOUT) {
            float v = W[wi];
            __nv_bfloat16 hi = __float2bfloat16_rn(v);
            g_wh[wi] = hi;
            g_wl[wi] = __float2bfloat16_rn(v - __bfloat162float(hi));
        }
    }
}

// ---------------------------------------------------------------------------
// C1: pack adjacency to nibble-permuted bitmask
// ---------------------------------------------------------------------------
__global__ __launch_bounds__(256) void adj_pack(const int* __restrict__ adj)
{
    int e = blockIdx.x * 256 + threadIdx.x;
    unsigned m = __ballot_sync(0xffffffffu, adj[e] > 0);
    if ((threadIdx.x & 31) == 0) g_adjbits[e >> 5] = permute_mask(m);
}

// ---------------------------------------------------------------------------
// K1: split-bf16 MMA GEMM  h = X @ W + b   (3 terms)  -- unchanged from R12
// ---------------------------------------------------------------------------
#define GB_SZ 25600
#define GM_ATT (2 * GB_SZ)
#define GEMM_SMEM (GM_ATT + 512)
#define G_NCHUNK (FIN / 32)

__global__ __launch_bounds__(256, 4) void gemm_mma(const float* __restrict__ bias,
                                                   const float* __restrict__ att)
{
    extern __shared__ char sp[];
    const uint32_t sb = smem_u32(sp);
    const int tid = threadIdx.x;
    const int w = tid >> 5, lane = tid & 31;
    const int wm = w & 3, wn = w >> 2;          // 4m x 2n warps
    const int bm = blockIdx.y * 128;
    const int hglob = blockIdx.x;               // one head per block
    const int bn = hglob * 64;

    float* sAtt = (float*)(sp + GM_ATT);
    if (tid < 128) sAtt[tid] = att[hglob * 128 + tid];

    auto stage = [&](int c, int buf) {
        const uint32_t bb = sb + buf * GB_SZ;
#pragma unroll
        for (int s = 0; s < 2; s++) {
            int u = tid * 2 + s;
            int row = u >> 2, q = u & 3;
            int swq = q ^ ((row >> 1) & 3);
            size_t asrc = (size_t)(bm + row) * FIN + c * 32 + q * 8;
            cp16(bb + row * 64 + swq * 16, &g_xh[asrc]);
            cp16(bb + 8192 + row * 64 + swq * 16, &g_xl[asrc]);
        }
        int kr = tid >> 3, c2 = tid & 7;
        size_t bsrc = (size_t)(c * 32 + kr) * FOUT + bn + c2 * 8;
        cp16(bb + 16384 + kr * 144 + c2 * 16, &g_wh[bsrc]);
        cp16(bb + 16384 + 4608 + kr * 144 + c2 * 16, &g_wl[bsrc]);
    };

    float acc[2][4][4];
#pragma unroll
    for (int i = 0; i < 2; i++)
#pragma unroll
        for (int j = 0; j < 4; j++)
#pragma unroll
            for (int r = 0; r < 4; r++) acc[i][j][r] = 0.f;

    stage(0, 0); CP_COMMIT();

#pragma unroll 1
    for (int c = 0; c < G_NCHUNK; c++) {
        const int buf = c & 1;
        if (c + 1 < G_NCHUNK) { stage(c + 1, buf ^ 1); CP_COMMIT(); CP_WAIT(1); }
        else CP_WAIT(0);
        __syncthreads();

        const uint32_t bb = sb + buf * GB_SZ;
#pragma unroll
        for (int kc = 0; kc < 2; kc++) {
            uint32_t ah[2][4], al[2][4];
#pragma unroll
            for (int mt = 0; mt < 2; mt++) {
                int mrow = wm * 32 + mt * 16 + (lane & 15);
                int cch = kc * 2 + (lane >> 4);
                uint32_t ao = mrow * 64 + ((cch ^ ((mrow >> 1) & 3)) * 16);
                ldsm_x4(ah[mt], bb + ao);
                ldsm_x4(al[mt], bb + 8192 + ao);
            }
            const int krow = kc * 16 + (lane & 15);
#pragma unroll
            for (int p = 0; p < 2; p++) {
                int col = wn * 32 + p * 16 + (lane >> 4) * 8;
                uint32_t bo = krow * 144 + col * 2;
                uint32_t bh4[4], bl4[4];
                ldsm_x4_t(bh4, bb + 16384 + bo);
                ldsm_x4_t(bl4, bb + 16384 + 4608 + bo);
#pragma unroll
                for (int mt = 0; mt < 2; mt++) {
                    mma16816(acc[mt][2 * p],     ah[mt], bh4[0], bh4[1]);
                    mma16816(acc[mt][2 * p],     ah[mt], bl4[0], bl4[1]);
                    mma16816(acc[mt][2 * p],     al[mt], bh4[0], bh4[1]);
                    mma16816(acc[mt][2 * p + 1], ah[mt], bh4[2], bh4[3]);
                    mma16816(acc[mt][2 * p + 1], ah[mt], bl4[2], bl4[3]);
                    mma16816(acc[mt][2 * p + 1], al[mt], bh4[2], bh4[3]);
                }
            }
        }
        __syncthreads();
    }

    // -------- epilogue: bias, g_hh (fp16), dt stash --------
    float* dt = (float*)sp;                      // 128 x 65 fp32 (bufs dead)
    const int g = lane >> 2, t = lane & 3;
#pragma unroll
    for (int mt = 0; mt < 2; mt++) {
        const int r0 = wm * 32 + mt * 16 + g;
        const int r1 = r0 + 8;
#pragma unroll
        for (int nt = 0; nt < 4; nt++) {
            int colL = wn * 32 + nt * 8 + 2 * t;
            float2 bv = *(const float2*)&bias[bn + colL];
            float c0 = acc[mt][nt][0] + bv.x;
            float c1 = acc[mt][nt][1] + bv.y;
            float c2 = acc[mt][nt][2] + bv.x;
            float c3 = acc[mt][nt][3] + bv.y;
            dt[r0 * 65 + colL] = c0; dt[r0 * 65 + colL + 1] = c1;
            dt[r1 * 65 + colL] = c2; dt[r1 * 65 + colL + 1] = c3;
            size_t d0 = (size_t)(bm + r0) * FOUT + bn + colL;
            size_t d1 = (size_t)(bm + r1) * FOUT + bn + colL;
            *(__half2*)&g_hh[d0] =
                __halves2half2(__float2half_rn(c0), __float2half_rn(c1));
            *(__half2*)&g_hh[d1] =
                __halves2half2(__float2half_rn(c2), __float2half_rn(c3));
        }
    }
    __syncthreads();

    // -------- fused scores: sdst fp32 + factorized F1/F2 fp16 --------
    {
        const int row = tid >> 1, half = tid & 1;
        float ssum = 0.f, dsum = 0.f;
#pragma unroll 8
        for (int d = half * 32; d < half * 32 + 32; d++) {
            float v = dt[row * 65 + d];
            ssum = fmaf(v, sAtt[d], ssum);
            dsum = fmaf(v, sAtt[64 + d], dsum);
        }
        ssum += __shfl_xor_sync(0xffffffffu, ssum, 1);
        dsum += __shfl_xor_sync(0xffffffffu, dsum, 1);
        if (half == 0) {
            const int nfull = bm + row;
            const int bq = nfull >> 10, n = nfull & 1023;
            const int o = (bq * HEADS + hglob) * NN + n;
            g_sdst[o] = dsum;
            g_f1[o] = __float2half_rn(__expf(ssum));
            g_f2[o] = __float2half_rn(__expf(ALPHA_LR * ssum));
        }
    }
}

// ---------------------------------------------------------------------------
// K3: fused masked softmax + PV (fp16) + ELU
// block = (b, h, 128 i-rows); 8 warps as 4m x 2n (warp m32 x n32) -- halves
// V ldsm traffic vs m16-exclusive/n64. Thread owns rows {r,r+8,r+16,r+24} of
// its m32 group; P computed register-direct (E*F*mask, LUT-expanded masks).
// 64-j tiles via 2-buffer prefetch-1 cp.async. Denominators via ones-MMA
// per m16 tile.
// smem per buf: V 9216 | mask 1024 = 10240, x2; F 4096; LUT 128.
// ---------------------------------------------------------------------------
#define AB_SZ 10240
#define AT_F (2 * AB_SZ)
#define AT_LUT (AT_F + 4096)
#define ATTN_SMEM (AT_LUT + 128)

__global__ __launch_bounds__(256, 3) void attn_mma(float* __restrict__ out)
{
    extern __shared__ char sp[];
    const uint32_t sb = smem_u32(sp);
    const int b = blockIdx.z, h = blockIdx.y;
    const int i0 = blockIdx.x * 128;
    const int tid = threadIdx.x;
    const int w = tid >> 5, lane = tid & 31;
    const int wm = w & 3, wn = w >> 2;          // 4m x 2n warps
    const int bh = b * HEADS + h;

    // LUT: nibble u -> two packed-fp16 0/1 masks
    if (tid < 16) {
        uint32_t u = tid;
        uint2 v;
        v.x = (u & 1u) * 0x3C00u + ((u >> 1) & 1u) * 0x3C000000u;
        v.y = ((u >> 2) & 1u) * 0x3C00u + ((u >> 3) & 1u) * 0x3C000000u;
        *(uint2*)(sp + AT_LUT + tid * 8) = v;
    }

    auto stageV = [&](int jt, int buf) {
        const uint32_t bb = sb + buf * AB_SZ;
        int k = tid >> 3, c = tid & 7;
#pragma unroll
        for (int s = 0; s < 2; s++) {
            int row = s * 32 + k;
            size_t src = (size_t)(b * NN + jt * 64 + row) * FOUT + h * DH + c * 8;
            cp16(bb + row * 144 + c * 16, &g_hh[src]);
        }
        if (tid < 128)
            cp8(bb + 9216 + tid * 8,
                &g_adjbits[(size_t)(b * NN + i0 + tid) * (NN / 32) + jt * 2]);
    };

    const int r = lane >> 2;
    const int rbase = i0 + wm * 32 + r;
    __half2 E1[4], E2[4];
#pragma unroll
    for (int m = 0; m < 4; m++) {
        float sd = g_sdst[bh * NN + rbase + m * 8];
        E1[m] = __half2half2(__float2half_rn(__expf(sd)));
        E2[m] = __half2half2(__float2half_rn(__expf(ALPHA_LR * sd)));
    }

    // group 0: F tables (2KB each) + V/mask tile 0
    if (tid < 128) cp16(sb + AT_F + tid * 16, &g_f1[bh * NN + tid * 8]);
    else cp16(sb + AT_F + 2048 + (tid - 128) * 16, &g_f2[bh * NN + (tid - 128) * 8]);
    stageV(0, 0); CP_COMMIT();

    float acc[2][4][4];
#pragma unroll
    for (int i = 0; i < 2; i++)
#pragma unroll
        for (int q = 0; q < 4; q++)
#pragma unroll
            for (int e = 0; e < 4; e++) acc[i][q][e] = 0.f;
    float accd0[4] = {0.f, 0.f, 0.f, 0.f};
    float accd1[4] = {0.f, 0.f, 0.f, 0.f};

    const char* spF = sp + AT_F;
    const uint2* lut = (const uint2*)(sp + AT_LUT);
    const int cq = (lane & 3) * 2;
    const int nib = (lane & 3) * 4;

#pragma unroll 1
    for (int jt = 0; jt < NN / 64; jt++) {
        const int buf = jt & 1;
        if (jt + 1 < NN / 64) { stageV(jt + 1, buf ^ 1); CP_COMMIT(); CP_WAIT(1); }
        else CP_WAIT(0);
        __syncthreads();

        const uint32_t bb = sb + buf * AB_SZ;
        const char* mbase = sp + buf * AB_SZ + 9216;
        uint2 mrow[4];
#pragma unroll
        for (int m = 0; m < 4; m++)
            mrow[m] = *(const uint2*)(mbase + (wm * 32 + r + m * 8) * 8);

#pragma unroll
        for (int kc = 0; kc < 4; kc++) {
            const int sh4 = (kc & 1) * 16 + nib;
            const int jo = jt * 128 + kc * 32 + cq * 2;   // bytes into F tables
            uint32_t f1A = *(const uint32_t*)(spF + jo);
            uint32_t f1B = *(const uint32_t*)(spF + jo + 16);
            uint32_t f2A = *(const uint32_t*)(spF + 2048 + jo);
            uint32_t f2B = *(const uint32_t*)(spF + 2048 + jo + 16);
            uint2 mk[4];
#pragma unroll
            for (int m = 0; m < 4; m++) {
                uint32_t word = (kc < 2) ? mrow[m].x : mrow[m].y;
                mk[m] = lut[(word >> sh4) & 0xFu];
            }
            uint32_t ah0[4], ah1[4];
            ah0[0] = ppair(f1A, f2A, E1[0], E2[0], mk[0].x);
            ah0[1] = ppair(f1A, f2A, E1[1], E2[1], mk[1].x);
            ah0[2] = ppair(f1B, f2B, E1[0], E2[0], mk[0].y);
            ah0[3] = ppair(f1B, f2B, E1[1], E2[1], mk[1].y);
            ah1[0] = ppair(f1A, f2A, E1[2], E2[2], mk[2].x);
            ah1[1] = ppair(f1A, f2A, E1[3], E2[3], mk[3].x);
            ah1[2] = ppair(f1B, f2B, E1[2], E2[2], mk[2].y);
            ah1[3] = ppair(f1B, f2B, E1[3], E2[3], mk[3].y);

            // denominators: row sums via all-ones B fragment
            mma16816h(accd0, ah0, ONESH2, ONESH2);
            mma16816h(accd1, ah1, ONESH2, ONESH2);

            const int krow = kc * 16 + (lane & 15);
#pragma unroll
            for (int p = 0; p < 2; p++) {
                int col = wn * 32 + p * 16 + (lane >> 4) * 8;
                uint32_t bh4[4];
                ldsm_x4_t(bh4, bb + (krow * 144 + col * 2));
                mma16816h(acc[0][2 * p],     ah0, bh4[0], bh4[1]);
                mma16816h(acc[0][2 * p + 1], ah0, bh4[2], bh4[3]);
                mma16816h(acc[1][2 * p],     ah1, bh4[0], bh4[1]);
                mma16816h(acc[1][2 * p + 1], ah1, bh4[2], bh4[3]);
            }
        }
        __syncthreads();
    }

    const float inv[4] = { 1.f / accd0[0], 1.f / accd0[2],
                           1.f / accd1[0], 1.f / accd1[2] };

    // epilogue: normalize, ELU, store (4 rows x 4 n-tiles)
#pragma unroll
    for (int m = 0; m < 2; m++) {
#pragma unroll
        for (int half = 0; half < 2; half++) {
            const int rowi = rbase + (m * 2 + half) * 8;
            const float iv = inv[m * 2 + half];
            const size_t rbytes = (size_t)(b * NN + rowi) * FOUT;
#pragma unroll
            for (int nt = 0; nt < 4; nt++) {
                int col = h * DH + wn * 32 + nt * 8 + cq;
                float o0 = acc[m][nt][half * 2]     * iv;
                float o1 = acc[m][nt][half * 2 + 1] * iv;
                o0 = (o0 > 0.f) ? o0 : expm1f(o0);
                o1 = (o1 > 0.f) ? o1 : expm1f(o1);
                *(float2*)&out[rbytes + col] = make_float2(o0, o1);
            }
        }
    }
}

// ---------------------------------------------------------------------------
extern "C" void kernel_launch(void* const* d_in, const int* in_sizes, int n_in,
                              void* d_out, int out_size)
{
    const float* x   = (const float*)d_in[0];   // (8,1024,512)
    const int*   adj = (const int*)d_in[1];     // (8,1024,1024)
    const float* Ww  = (const float*)d_in[2];   // (512,512)
    const float* Wb  = (const float*)d_in[3];   // (512,)
    const float* att = (const float*)d_in[4];   // (8,128)
    float* out = (float*)d_out;                 // (8,1024,512)

    cudaFuncSetAttribute(gemm_mma, cudaFuncAttributeMaxDynamicSharedMemorySize,
                         GEMM_SMEM);
    cudaFuncSetAttribute(attn_mma, cudaFuncAttributeMaxDynamicSharedMemorySize,
                         ATTN_SMEM);

    const int nconv = BATCH * NN * FIN + FIN * FOUT;
    conv_xw<<<(nconv + 255) / 256, 256>>>(x, Ww);
    adj_pack<<<(BATCH * NN * NN) / 256, 256>>>(adj);
    gemm_mma<<<dim3(HEADS, (BATCH * NN) / 128), 256, GEMM_SMEM>>>(Wb, att);
    attn_mma<<<dim3(NN / 128, HEADS, BATCH), 256, ATTN_SMEM>>>(out);
}

// round 14
// speedup vs baseline: 1.0667x; 1.0667x over previous
#include <cuda_runtime.h>
#include <cuda_bf16.h>
#include <cuda_fp16.h>
#include <math.h>
#include <stdint.h>

// Problem constants: B=8, N=1024, Fin=512, Fout=512, H=8, dh=64
#define BATCH 8
#define NN    1024
#define FIN   512
#define FOUT  512
#define HEADS 8
#define DH    64
#define ALPHA_LR 0.2f

// ---------------- device scratch ----------------
__device__ __nv_bfloat16 g_xh[BATCH * NN * FIN];
__device__ __nv_bfloat16 g_xl[BATCH * NN * FIN];
__device__ __nv_bfloat16 g_wh[FIN * FOUT];
__device__ __nv_bfloat16 g_wl[FIN * FOUT];
__device__ __half        g_hh[BATCH * NN * FOUT];    // h (fp16)
__device__ float         g_sdst[BATCH * HEADS * NN];
__device__ __half        g_f1[BATCH * HEADS * NN];   // exp(ss) fp16
__device__ __half        g_f2[BATCH * HEADS * NN];   // exp(0.2*ss) fp16
__device__ unsigned      g_adjbits[BATCH * NN * (NN / 32)];  // nibble-permuted

// ---------------- PTX helpers ----------------
static __device__ __forceinline__ uint32_t smem_u32(const void* p) {
    return (uint32_t)__cvta_generic_to_shared(p);
}
static __device__ __forceinline__ void ldsm_x4(uint32_t* r, uint32_t a) {
    asm volatile("ldmatrix.sync.aligned.m8n8.x4.shared.b16 {%0,%1,%2,%3}, [%4];"
        : "=r"(r[0]), "=r"(r[1]), "=r"(r[2]), "=r"(r[3]) : "r"(a));
}
static __device__ __forceinline__ void ldsm_x4_t(uint32_t* r, uint32_t a) {
    asm volatile("ldmatrix.sync.aligned.m8n8.x4.trans.shared.b16 {%0,%1,%2,%3}, [%4];"
        : "=r"(r[0]), "=r"(r[1]), "=r"(r[2]), "=r"(r[3]) : "r"(a));
}
// bf16 MMA (GEMM)
static __device__ __forceinline__ void mma16816(float* d, const uint32_t* a,
                                                uint32_t b0, uint32_t b1) {
    asm volatile(
        "mma.sync.aligned.m16n8k16.row.col.f32.bf16.bf16.f32 "
        "{%0,%1,%2,%3}, {%4,%5,%6,%7}, {%8,%9}, {%0,%1,%2,%3};"
        : "+f"(d[0]), "+f"(d[1]), "+f"(d[2]), "+f"(d[3])
        : "r"(a[0]), "r"(a[1]), "r"(a[2]), "r"(a[3]), "r"(b0), "r"(b1));
}
// fp16 MMA (attention P*V)
static __device__ __forceinline__ void mma16816h(float* d, const uint32_t* a,
                                                 uint32_t b0, uint32_t b1) {
    asm volatile(
        "mma.sync.aligned.m16n8k16.row.col.f32.f16.f16.f32 "
        "{%0,%1,%2,%3}, {%4,%5,%6,%7}, {%8,%9}, {%0,%1,%2,%3};"
        : "+f"(d[0]), "+f"(d[1]), "+f"(d[2]), "+f"(d[3])
        : "r"(a[0]), "r"(a[1]), "r"(a[2]), "r"(a[3]), "r"(b0), "r"(b1));
}
static __device__ __forceinline__ void cp16(uint32_t dst, const void* src) {
    asm volatile("cp.async.cg.shared.global [%0], [%1], 16;"
        :: "r"(dst), "l"(src) : "memory");
}
static __device__ __forceinline__ void cp8(uint32_t dst, const void* src) {
    asm volatile("cp.async.ca.shared.global [%0], [%1], 8;"
        :: "r"(dst), "l"(src) : "memory");
}
#define CP_COMMIT() asm volatile("cp.async.commit_group;" ::: "memory")
#define CP_WAIT(n)  asm volatile("cp.async.wait_group %0;" :: "n"(n) : "memory")

// packed p-pair: p = max(E1*F1, E2*F2) * mask   (exp(leakyrelu) identity)
static __device__ __forceinline__ uint32_t ppair(uint32_t f1p, uint32_t f2p,
                                                 __half2 E1, __half2 E2,
                                                 uint32_t mk) {
    __half2 a = __hmul2(E1, *(__half2*)&f1p);
    __half2 b = __hmul2(E2, *(__half2*)&f2p);
    __half2 p = __hmul2(__hmax2(a, b), *(__half2*)&mk);
    return *(uint32_t*)&p;
}
#define ONESH2 0x3C003C00u

// nibble permutation: nibble q of each 16-bit half holds bits {2q,2q+1,2q+8,2q+9}
static __device__ __forceinline__ uint32_t permute_mask(uint32_t m) {
    return (m & 0x00030003u)
         | ((m & 0x000C000Cu) << 2)
         | ((m & 0x00300030u) << 4)
         | ((m & 0x00C000C0u) << 6)
         | ((m & 0x03000300u) >> 6)
         | ((m & 0x0C000C00u) >> 4)
         | ((m & 0x30003000u) >> 2)
         |  (m & 0xC000C000u);
}

// ---------------------------------------------------------------------------
// C0: split X and W into bf16 hi/lo
// ---------------------------------------------------------------------------
__global__ __launch_bounds__(256) void conv_xw(const float* __restrict__ X,
                                               const float* __restrict__ W)
{
    int idx = blockIdx.x * 256 + threadIdx.x;
    const int NX = BATCH * NN * FIN;
    if (idx < NX) {
        float v = X[idx];
        __nv_bfloat16 hi = __float2bfloat16_rn(v);
        g_xh[idx] = hi;
        g_xl[idx] = __float2bfloat16_rn(v - __bfloat162float(hi));
    } else {
        int wi = idx - NX;
        if (wi < FIN * FOUT) {
            float v = W[wi];
            __nv_bfloat16 hi = __float2bfloat16_rn(v);
            g_wh[wi] = hi;
            g_wl[wi] = __float2bfloat16_rn(v - __bfloat162float(hi));
        }
    }
}

// ---------------------------------------------------------------------------
// C1: pack adjacency to nibble-permuted bitmask
// ---------------------------------------------------------------------------
__global__ __launch_bounds__(256) void adj_pack(const int* __restrict__ adj)
{
    int e = blockIdx.x * 256 + threadIdx.x;
    unsigned m = __ballot_sync(0xffffffffu, adj[e] > 0);
    if ((threadIdx.x & 31) == 0) g_adjbits[e >> 5] = permute_mask(m);
}

// ---------------------------------------------------------------------------
// K1: split-bf16 MMA GEMM  h = X @ W + b   (3 terms)  -- unchanged from R12
// ---------------------------------------------------------------------------
#define GB_SZ 25600
#define GM_ATT (2 * GB_SZ)
#define GEMM_SMEM (GM_ATT + 512)
#define G_NCHUNK (FIN / 32)

__global__ __launch_bounds__(256, 4) void gemm_mma(const float* __restrict__ bias,
                                                   const float* __restrict__ att)
{
    extern __shared__ char sp[];
    const uint32_t sb = smem_u32(sp);
    const int tid = threadIdx.x;
    const int w = tid >> 5, lane = tid & 31;
    const int wm = w & 3, wn = w >> 2;          // 4m x 2n warps
    const int bm = blockIdx.y * 128;
    const int hglob = blockIdx.x;               // one head per block
    const int bn = hglob * 64;

    float* sAtt = (float*)(sp + GM_ATT);
    if (tid < 128) sAtt[tid] = att[hglob * 128 + tid];

    auto stage = [&](int c, int buf) {
        const uint32_t bb = sb + buf * GB_SZ;
#pragma unroll
        for (int s = 0; s < 2; s++) {
            int u = tid * 2 + s;
            int row = u >> 2, q = u & 3;
            int swq = q ^ ((row >> 1) & 3);
            size_t asrc = (size_t)(bm + row) * FIN + c * 32 + q * 8;
            cp16(bb + row * 64 + swq * 16, &g_xh[asrc]);
            cp16(bb + 8192 + row * 64 + swq * 16, &g_xl[asrc]);
        }
        int kr = tid >> 3, c2 = tid & 7;
        size_t bsrc = (size_t)(c * 32 + kr) * FOUT + bn + c2 * 8;
        cp16(bb + 16384 + kr * 144 + c2 * 16, &g_wh[bsrc]);
        cp16(bb + 16384 + 4608 + kr * 144 + c2 * 16, &g_wl[bsrc]);
    };

    float acc[2][4][4];
#pragma unroll
    for (int i = 0; i < 2; i++)
#pragma unroll
        for (int j = 0; j < 4; j++)
#pragma unroll
            for (int r = 0; r < 4; r++) acc[i][j][r] = 0.f;

    stage(0, 0); CP_COMMIT();

#pragma unroll 1
    for (int c = 0; c < G_NCHUNK; c++) {
        const int buf = c & 1;
        if (c + 1 < G_NCHUNK) { stage(c + 1, buf ^ 1); CP_COMMIT(); CP_WAIT(1); }
        else CP_WAIT(0);
        __syncthreads();

        const uint32_t bb = sb + buf * GB_SZ;
#pragma unroll
        for (int kc = 0; kc < 2; kc++) {
            uint32_t ah[2][4], al[2][4];
#pragma unroll
            for (int mt = 0; mt < 2; mt++) {
                int mrow = wm * 32 + mt * 16 + (lane & 15);
                int cch = kc * 2 + (lane >> 4);
                uint32_t ao = mrow * 64 + ((cch ^ ((mrow >> 1) & 3)) * 16);
                ldsm_x4(ah[mt], bb + ao);
                ldsm_x4(al[mt], bb + 8192 + ao);
            }
            const int krow = kc * 16 + (lane & 15);
#pragma unroll
            for (int p = 0; p < 2; p++) {
                int col = wn * 32 + p * 16 + (lane >> 4) * 8;
                uint32_t bo = krow * 144 + col * 2;
                uint32_t bh4[4], bl4[4];
                ldsm_x4_t(bh4, bb + 16384 + bo);
                ldsm_x4_t(bl4, bb + 16384 + 4608 + bo);
#pragma unroll
                for (int mt = 0; mt < 2; mt++) {
                    mma16816(acc[mt][2 * p],     ah[mt], bh4[0], bh4[1]);
                    mma16816(acc[mt][2 * p],     ah[mt], bl4[0], bl4[1]);
                    mma16816(acc[mt][2 * p],     al[mt], bh4[0], bh4[1]);
                    mma16816(acc[mt][2 * p + 1], ah[mt], bh4[2], bh4[3]);
                    mma16816(acc[mt][2 * p + 1], ah[mt], bl4[2], bl4[3]);
                    mma16816(acc[mt][2 * p + 1], al[mt], bh4[2], bh4[3]);
                }
            }
        }
        __syncthreads();
    }

    // -------- epilogue: bias, g_hh (fp16), dt stash --------
    float* dt = (float*)sp;                      // 128 x 65 fp32 (bufs dead)
    const int g = lane >> 2, t = lane & 3;
#pragma unroll
    for (int mt = 0; mt < 2; mt++) {
        const int r0 = wm * 32 + mt * 16 + g;
        const int r1 = r0 + 8;
#pragma unroll
        for (int nt = 0; nt < 4; nt++) {
            int colL = wn * 32 + nt * 8 + 2 * t;
            float2 bv = *(const float2*)&bias[bn + colL];
            float c0 = acc[mt][nt][0] + bv.x;
            float c1 = acc[mt][nt][1] + bv.y;
            float c2 = acc[mt][nt][2] + bv.x;
            float c3 = acc[mt][nt][3] + bv.y;
            dt[r0 * 65 + colL] = c0; dt[r0 * 65 + colL + 1] = c1;
            dt[r1 * 65 + colL] = c2; dt[r1 * 65 + colL + 1] = c3;
            size_t d0 = (size_t)(bm + r0) * FOUT + bn + colL;
            size_t d1 = (size_t)(bm + r1) * FOUT + bn + colL;
            *(__half2*)&g_hh[d0] =
                __halves2half2(__float2half_rn(c0), __float2half_rn(c1));
            *(__half2*)&g_hh[d1] =
                __halves2half2(__float2half_rn(c2), __float2half_rn(c3));
        }
    }
    __syncthreads();

    // -------- fused scores: sdst fp32 + factorized F1/F2 fp16 --------
    {
        const int row = tid >> 1, half = tid & 1;
        float ssum = 0.f, dsum = 0.f;
#pragma unroll 8
        for (int d = half * 32; d < half * 32 + 32; d++) {
            float v = dt[row * 65 + d];
            ssum = fmaf(v, sAtt[d], ssum);
            dsum = fmaf(v, sAtt[64 + d], dsum);
        }
        ssum += __shfl_xor_sync(0xffffffffu, ssum, 1);
        dsum += __shfl_xor_sync(0xffffffffu, dsum, 1);
        if (half == 0) {
            const int nfull = bm + row;
            const int bq = nfull >> 10, n = nfull & 1023;
            const int o = (bq * HEADS + hglob) * NN + n;
            g_sdst[o] = dsum;
            g_f1[o] = __float2half_rn(__expf(ssum));
            g_f2[o] = __float2half_rn(__expf(ALPHA_LR * ssum));
        }
    }
}

// ---------------------------------------------------------------------------
// K3: fused masked softmax + PV (fp16) + ELU
// block = (b, h, 128 i-rows); 8 warps each own m16 exclusively (warp n64).
// 64-j tiles: V (64x64 fp16, pitch 144B) + permuted bitmask rows (8B/row)
// via 2-buffer prefetch-1 cp.async. Mask expansion via 16-entry uint2 LUT
// (nibble -> two packed-fp16 0/1 masks). p = max(E1*F1, E2*F2) * mask.
// Denominator via n8 MMA against constant all-ones B fragment.
// smem per buf: V 9216 | mask 1024 = 10240, x2; F tables 4096; LUT 128.
// ---------------------------------------------------------------------------
#define AB_SZ 10240
#define AT_F (2 * AB_SZ)
#define AT_LUT (AT_F + 4096)
#define ATTN_SMEM (AT_LUT + 128)

__global__ __launch_bounds__(256, 4) void attn_mma(float* __restrict__ out)
{
    extern __shared__ char sp[];
    const uint32_t sb = smem_u32(sp);
    const int b = blockIdx.z, h = blockIdx.y;
    const int i0 = blockIdx.x * 128;
    const int tid = threadIdx.x;
    const int w = tid >> 5, lane = tid & 31;
    const int bh = b * HEADS + h;

    // LUT: nibble u -> two packed-fp16 0/1 masks
    if (tid < 16) {
        uint32_t u = tid;
        uint2 v;
        v.x = (u & 1u) * 0x3C00u + ((u >> 1) & 1u) * 0x3C000000u;
        v.y = ((u >> 2) & 1u) * 0x3C00u + ((u >> 3) & 1u) * 0x3C000000u;
        *(uint2*)(sp + AT_LUT + tid * 8) = v;
    }

    auto stageV = [&](int jt, int buf) {
        const uint32_t bb = sb + buf * AB_SZ;
        int k = tid >> 3, c = tid & 7;
#pragma unroll
        for (int s = 0; s < 2; s++) {
            int row = s * 32 + k;
            size_t src = (size_t)(b * NN + jt * 64 + row) * FOUT + h * DH + c * 8;
            cp16(bb + row * 144 + c * 16, &g_hh[src]);
        }
        if (tid < 128)
            cp8(bb + 9216 + tid * 8,
                &g_adjbits[(size_t)(b * NN + i0 + tid) * (NN / 32) + jt * 2]);
    };

    const int r = lane >> 2;
    const float sd0 = g_sdst[bh * NN + i0 + w * 16 + r];
    const float sd1 = g_sdst[bh * NN + i0 + w * 16 + r + 8];
    const __half2 E10 = __half2half2(__float2half_rn(__expf(sd0)));
    const __half2 E20 = __half2half2(__float2half_rn(__expf(ALPHA_LR * sd0)));
    const __half2 E11 = __half2half2(__float2half_rn(__expf(sd1)));
    const __half2 E21 = __half2half2(__float2half_rn(__expf(ALPHA_LR * sd1)));

    // group 0: F tables (2KB each) + V/mask tile 0
    if (tid < 128) cp16(sb + AT_F + tid * 16, &g_f1[bh * NN + tid * 8]);
    else cp16(sb + AT_F + 2048 + (tid - 128) * 16, &g_f2[bh * NN + (tid - 128) * 8]);
    stageV(0, 0); CP_COMMIT();

    float acc[8][4];
#pragma unroll
    for (int i = 0; i < 8; i++)
#pragma unroll
        for (int q = 0; q < 4; q++) acc[i][q] = 0.f;
    float accd[4] = {0.f, 0.f, 0.f, 0.f};

    const char* spF = sp + AT_F;
    const uint2* lut = (const uint2*)(sp + AT_LUT);
    const int cq = (lane & 3) * 2;
    const int nib = (lane & 3) * 4;

#pragma unroll 1
    for (int jt = 0; jt < NN / 64; jt++) {
        const int buf = jt & 1;
        if (jt + 1 < NN / 64) { stageV(jt + 1, buf ^ 1); CP_COMMIT(); CP_WAIT(1); }
        else CP_WAIT(0);
        __syncthreads();

        const uint32_t bb = sb + buf * AB_SZ;
        const uint2 mrow0 = *(const uint2*)(sp + buf * AB_SZ + 9216 +
                                            (w * 16 + r) * 8);
        const uint2 mrow1 = *(const uint2*)(sp + buf * AB_SZ + 9216 +
                                            (w * 16 + r + 8) * 8);
#pragma unroll
        for (int kc = 0; kc < 4; kc++) {
            const uint32_t w0 = (kc < 2) ? mrow0.x : mrow0.y;
            const uint32_t w1 = (kc < 2) ? mrow1.x : mrow1.y;
            const int sh4 = (kc & 1) * 16 + nib;
            const uint2 mk0 = lut[(w0 >> sh4) & 0xFu];
            const uint2 mk1 = lut[(w1 >> sh4) & 0xFu];
            const int jo = jt * 128 + kc * 32 + cq * 2;   // bytes into F tables
            uint32_t f1A = *(const uint32_t*)(spF + jo);
            uint32_t f1B = *(const uint32_t*)(spF + jo + 16);
            uint32_t f2A = *(const uint32_t*)(spF + 2048 + jo);
            uint32_t f2B = *(const uint32_t*)(spF + 2048 + jo + 16);
            uint32_t ah[4];
            ah[0] = ppair(f1A, f2A, E10, E20, mk0.x);
            ah[1] = ppair(f1A, f2A, E11, E21, mk1.x);
            ah[2] = ppair(f1B, f2B, E10, E20, mk0.y);
            ah[3] = ppair(f1B, f2B, E11, E21, mk1.y);

            // denominator: row sums via all-ones B fragment
            mma16816h(accd, ah, ONESH2, ONESH2);

            const int krow = kc * 16 + (lane & 15);
#pragma unroll
            for (int nt2 = 0; nt2 < 4; nt2++) {
                int col = nt2 * 16 + (lane >> 4) * 8;
                uint32_t bh4[4];
                ldsm_x4_t(bh4, bb + (krow * 144 + col * 2));
                mma16816h(acc[nt2 * 2],     ah, bh4[0], bh4[1]);
                mma16816h(acc[nt2 * 2 + 1], ah, bh4[2], bh4[3]);
            }
        }
        __syncthreads();
    }

    const float inv0 = 1.f / accd[0];
    const float inv1 = 1.f / accd[2];

    // epilogue: normalize, ELU, store
    const size_t row0 = (size_t)(b * NN + i0 + w * 16 + r);
    const size_t row1 = row0 + 8;
#pragma unroll
    for (int nt = 0; nt < 8; nt++) {
        int col = h * DH + nt * 8 + cq;
        float o0 = acc[nt][0] * inv0; o0 = (o0 > 0.f) ? o0 : expm1f(o0);
        float o1 = acc[nt][1] * inv0; o1 = (o1 > 0.f) ? o1 : expm1f(o1);
        float o2 = acc[nt][2] * inv1; o2 = (o2 > 0.f) ? o2 : expm1f(o2);
        float o3 = acc[nt][3] * inv1; o3 = (o3 > 0.f) ? o3 : expm1f(o3);
        *(float2*)&out[row0 * FOUT + col] = make_float2(o0, o1);
        *(float2*)&out[row1 * FOUT + col] = make_float2(o2, o3);
    }
}

// ---------------------------------------------------------------------------
extern "C" void kernel_launch(void* const* d_in, const int* in_sizes, int n_in,
                              void* d_out, int out_size)
{
    const float* x   = (const float*)d_in[0];   // (8,1024,512)
    const int*   adj = (const int*)d_in[1];     // (8,1024,1024)
    const float* Ww  = (const float*)d_in[2];   // (512,512)
    const float* Wb  = (const float*)d_in[3];   // (512,)
    const float* att = (const float*)d_in[4];   // (8,128)
    float* out = (float*)d_out;                 // (8,1024,512)

    cudaFuncSetAttribute(gemm_mma, cudaFuncAttributeMaxDynamicSharedMemorySize,
                         GEMM_SMEM);
    cudaFuncSetAttribute(attn_mma, cudaFuncAttributeMaxDynamicSharedMemorySize,
                         ATTN_SMEM);

    const int nconv = BATCH * NN * FIN + FIN * FOUT;
    conv_xw<<<(nconv + 255) / 256, 256>>>(x, Ww);
    adj_pack<<<(BATCH * NN * NN) / 256, 256>>>(adj);
    gemm_mma<<<dim3(HEADS, (BATCH * NN) / 128), 256, GEMM_SMEM>>>(Wb, att);
    attn_mma<<<dim3(NN / 128, HEADS, BATCH), 256, ATTN_SMEM>>>(out);
}

// round 15
// speedup vs baseline: 1.0848x; 1.0170x over previous
#include <cuda_runtime.h>
#include <cuda_bf16.h>
#include <cuda_fp16.h>
#include <math.h>
#include <stdint.h>

// Problem constants: B=8, N=1024, Fin=512, Fout=512, H=8, dh=64
#define BATCH 8
#define NN    1024
#define FIN   512
#define FOUT  512
#define HEADS 8
#define DH    64
#define ALPHA_LR 0.2f

// ---------------- device scratch ----------------
__device__ __nv_bfloat16 g_xh[BATCH * NN * FIN];
__device__ __nv_bfloat16 g_xl[BATCH * NN * FIN];
__device__ __nv_bfloat16 g_wh[FIN * FOUT];
__device__ __nv_bfloat16 g_wl[FIN * FOUT];
__device__ __half        g_hh[BATCH * NN * FOUT];    // h (fp16)
__device__ float         g_sdst[BATCH * HEADS * NN];
__device__ __half        g_f1[BATCH * HEADS * NN];   // exp(ss) fp16
__device__ __half        g_f2[BATCH * HEADS * NN];   // exp(0.2*ss) fp16
__device__ unsigned      g_adjbits[BATCH * NN * (NN / 32)];

// ---------------- PTX helpers ----------------
static __device__ __forceinline__ uint32_t smem_u32(const void* p) {
    return (uint32_t)__cvta_generic_to_shared(p);
}
static __device__ __forceinline__ void ldsm_x4(uint32_t* r, uint32_t a) {
    asm volatile("ldmatrix.sync.aligned.m8n8.x4.shared.b16 {%0,%1,%2,%3}, [%4];"
        : "=r"(r[0]), "=r"(r[1]), "=r"(r[2]), "=r"(r[3]) : "r"(a));
}
static __device__ __forceinline__ void ldsm_x4_t(uint32_t* r, uint32_t a) {
    asm volatile("ldmatrix.sync.aligned.m8n8.x4.trans.shared.b16 {%0,%1,%2,%3}, [%4];"
        : "=r"(r[0]), "=r"(r[1]), "=r"(r[2]), "=r"(r[3]) : "r"(a));
}
// bf16 MMA (GEMM)
static __device__ __forceinline__ void mma16816(float* d, const uint32_t* a,
                                                uint32_t b0, uint32_t b1) {
    asm volatile(
        "mma.sync.aligned.m16n8k16.row.col.f32.bf16.bf16.f32 "
        "{%0,%1,%2,%3}, {%4,%5,%6,%7}, {%8,%9}, {%0,%1,%2,%3};"
        : "+f"(d[0]), "+f"(d[1]), "+f"(d[2]), "+f"(d[3])
        : "r"(a[0]), "r"(a[1]), "r"(a[2]), "r"(a[3]), "r"(b0), "r"(b1));
}
// fp16 MMA (attention P*V)
static __device__ __forceinline__ void mma16816h(float* d, const uint32_t* a,
                                                 uint32_t b0, uint32_t b1) {
    asm volatile(
        "mma.sync.aligned.m16n8k16.row.col.f32.f16.f16.f32 "
        "{%0,%1,%2,%3}, {%4,%5,%6,%7}, {%8,%9}, {%0,%1,%2,%3};"
        : "+f"(d[0]), "+f"(d[1]), "+f"(d[2]), "+f"(d[3])
        : "r"(a[0]), "r"(a[1]), "r"(a[2]), "r"(a[3]), "r"(b0), "r"(b1));
}
static __device__ __forceinline__ void cp16(uint32_t dst, const void* src) {
    asm volatile("cp.async.cg.shared.global [%0], [%1], 16;"
        :: "r"(dst), "l"(src) : "memory");
}
static __device__ __forceinline__ void cp8(uint32_t dst, const void* src) {
    asm volatile("cp.async.ca.shared.global [%0], [%1], 8;"
        :: "r"(dst), "l"(src) : "memory");
}
#define CP_COMMIT() asm volatile("cp.async.commit_group;" ::: "memory")
#define CP_WAIT(n)  asm volatile("cp.async.wait_group %0;" :: "n"(n) : "memory")

// expand bits (sh, sh+1) of w to packed fp16 {b0?1:0, b1?1:0}
static __device__ __forceinline__ uint32_t mkexp(uint32_t w, int sh) {
    uint32_t t = w >> sh;
    return (t & 1u) * 0x3C00u + (t & 2u) * 0x1E000000u;
}
// packed p-pair: p = max(E1*F1, E2*F2) * mask   (exp(leakyrelu) identity)
static __device__ __forceinline__ uint32_t ppair(uint32_t f1p, uint32_t f2p,
                                                 __half2 E1, __half2 E2,
                                                 uint32_t mk) {
    __half2 a = __hmul2(E1, *(__half2*)&f1p);
    __half2 b = __hmul2(E2, *(__half2*)&f2p);
    __half2 p = __hmul2(__hmax2(a, b), *(__half2*)&mk);
    return *(uint32_t*)&p;
}
#define ONESH2 0x3C003C00u

// ---------------------------------------------------------------------------
// C0: split X and W into bf16 hi/lo
// ---------------------------------------------------------------------------
__global__ __launch_bounds__(256) void conv_xw(const float* __restrict__ X,
                                               const float* __restrict__ W)
{
    int idx = blockIdx.x * 256 + threadIdx.x;
    const int NX = BATCH * NN * FIN;
    if (idx < NX) {
        float v = X[idx];
        __nv_bfloat16 hi = __float2bfloat16_rn(v);
        g_xh[idx] = hi;
        g_xl[idx] = __float2bfloat16_rn(v - __bfloat162float(hi));
    } else {
        int wi = idx - NX;
        if (wi < FIN * FOUT) {
            float v = W[wi];
            __nv_bfloat16 hi = __float2bfloat16_rn(v);
            g_wh[wi] = hi;
            g_wl[wi] = __float2bfloat16_rn(v - __bfloat162float(hi));
        }
    }
}

// ---------------------------------------------------------------------------
// C1: pack adjacency to bitmask (plain bit order, matches mkexp)
// ---------------------------------------------------------------------------
__global__ __launch_bounds__(256) void adj_pack(const int* __restrict__ adj)
{
    int e = blockIdx.x * 256 + threadIdx.x;
    unsigned m = __ballot_sync(0xffffffffu, adj[e] > 0);
    if ((threadIdx.x & 31) == 0) g_adjbits[e >> 5] = m;
}

// ---------------------------------------------------------------------------
// K1: split-bf16 MMA GEMM  h = X @ W + b   (3 terms)  -- R12 version (best)
// block tile 128m x 64n (one head wide), 8 warps 4m x 2n (warp m32 x n32).
// k-chunks of 32, 2-buffer prefetch-1 cp.async pipeline.
// A tiles XOR-swizzled (pitch 64B) -> smem 51.2KB -> occupancy 4, single wave.
// ---------------------------------------------------------------------------
#define GB_SZ 25600
#define GM_ATT (2 * GB_SZ)
#define GEMM_SMEM (GM_ATT + 512)
#define G_NCHUNK (FIN / 32)

__global__ __launch_bounds__(256, 4) void gemm_mma(const float* __restrict__ bias,
                                                   const float* __restrict__ att)
{
    extern __shared__ char sp[];
    const uint32_t sb = smem_u32(sp);
    const int tid = threadIdx.x;
    const int w = tid >> 5, lane = tid & 31;
    const int wm = w & 3, wn = w >> 2;          // 4m x 2n warps
    const int bm = blockIdx.y * 128;
    const int hglob = blockIdx.x;               // one head per block
    const int bn = hglob * 64;

    float* sAtt = (float*)(sp + GM_ATT);
    if (tid < 128) sAtt[tid] = att[hglob * 128 + tid];

    auto stage = [&](int c, int buf) {
        const uint32_t bb = sb + buf * GB_SZ;
#pragma unroll
        for (int s = 0; s < 2; s++) {
            int u = tid * 2 + s;
            int row = u >> 2, q = u & 3;
            int swq = q ^ ((row >> 1) & 3);
            size_t asrc = (size_t)(bm + row) * FIN + c * 32 + q * 8;
            cp16(bb + row * 64 + swq * 16, &g_xh[asrc]);
            cp16(bb + 8192 + row * 64 + swq * 16, &g_xl[asrc]);
        }
        int kr = tid >> 3, c2 = tid & 7;
        size_t bsrc = (size_t)(c * 32 + kr) * FOUT + bn + c2 * 8;
        cp16(bb + 16384 + kr * 144 + c2 * 16, &g_wh[bsrc]);
        cp16(bb + 16384 + 4608 + kr * 144 + c2 * 16, &g_wl[bsrc]);
    };

    float acc[2][4][4];
#pragma unroll
    for (int i = 0; i < 2; i++)
#pragma unroll
        for (int j = 0; j < 4; j++)
#pragma unroll
            for (int r = 0; r < 4; r++) acc[i][j][r] = 0.f;

    stage(0, 0); CP_COMMIT();

#pragma unroll 1
    for (int c = 0; c < G_NCHUNK; c++) {
        const int buf = c & 1;
        if (c + 1 < G_NCHUNK) { stage(c + 1, buf ^ 1); CP_COMMIT(); CP_WAIT(1); }
        else CP_WAIT(0);
        __syncthreads();

        const uint32_t bb = sb + buf * GB_SZ;
#pragma unroll
        for (int kc = 0; kc < 2; kc++) {
            uint32_t ah[2][4], al[2][4];
#pragma unroll
            for (int mt = 0; mt < 2; mt++) {
                int mrow = wm * 32 + mt * 16 + (lane & 15);
                int cch = kc * 2 + (lane >> 4);
                uint32_t ao = mrow * 64 + ((cch ^ ((mrow >> 1) & 3)) * 16);
                ldsm_x4(ah[mt], bb + ao);
                ldsm_x4(al[mt], bb + 8192 + ao);
            }
            const int krow = kc * 16 + (lane & 15);
#pragma unroll
            for (int p = 0; p < 2; p++) {
                int col = wn * 32 + p * 16 + (lane >> 4) * 8;
                uint32_t bo = krow * 144 + col * 2;
                uint32_t bh4[4], bl4[4];
                ldsm_x4_t(bh4, bb + 16384 + bo);
                ldsm_x4_t(bl4, bb + 16384 + 4608 + bo);
#pragma unroll
                for (int mt = 0; mt < 2; mt++) {
                    mma16816(acc[mt][2 * p],     ah[mt], bh4[0], bh4[1]);
                    mma16816(acc[mt][2 * p],     ah[mt], bl4[0], bl4[1]);
                    mma16816(acc[mt][2 * p],     al[mt], bh4[0], bh4[1]);
                    mma16816(acc[mt][2 * p + 1], ah[mt], bh4[2], bh4[3]);
                    mma16816(acc[mt][2 * p + 1], ah[mt], bl4[2], bl4[3]);
                    mma16816(acc[mt][2 * p + 1], al[mt], bh4[2], bh4[3]);
                }
            }
        }
        __syncthreads();
    }

    // -------- epilogue: bias, g_hh (fp16), dt stash --------
    float* dt = (float*)sp;                      // 128 x 65 fp32 (bufs dead)
    const int g = lane >> 2, t = lane & 3;
#pragma unroll
    for (int mt = 0; mt < 2; mt++) {
        const int r0 = wm * 32 + mt * 16 + g;
        const int r1 = r0 + 8;
#pragma unroll
        for (int nt = 0; nt < 4; nt++) {
            int colL = wn * 32 + nt * 8 + 2 * t;
            float2 bv = *(const float2*)&bias[bn + colL];
            float c0 = acc[mt][nt][0] + bv.x;
            float c1 = acc[mt][nt][1] + bv.y;
            float c2 = acc[mt][nt][2] + bv.x;
            float c3 = acc[mt][nt][3] + bv.y;
            dt[r0 * 65 + colL] = c0; dt[r0 * 65 + colL + 1] = c1;
            dt[r1 * 65 + colL] = c2; dt[r1 * 65 + colL + 1] = c3;
            size_t d0 = (size_t)(bm + r0) * FOUT + bn + colL;
            size_t d1 = (size_t)(bm + r1) * FOUT + bn + colL;
            *(__half2*)&g_hh[d0] =
                __halves2half2(__float2half_rn(c0), __float2half_rn(c1));
            *(__half2*)&g_hh[d1] =
                __halves2half2(__float2half_rn(c2), __float2half_rn(c3));
        }
    }
    __syncthreads();

    // -------- fused scores: sdst fp32 + factorized F1/F2 fp16 --------
    {
        const int row = tid >> 1, half = tid & 1;
        float ssum = 0.f, dsum = 0.f;
#pragma unroll 8
        for (int d = half * 32; d < half * 32 + 32; d++) {
            float v = dt[row * 65 + d];
            ssum = fmaf(v, sAtt[d], ssum);
            dsum = fmaf(v, sAtt[64 + d], dsum);
        }
        ssum += __shfl_xor_sync(0xffffffffu, ssum, 1);
        dsum += __shfl_xor_sync(0xffffffffu, dsum, 1);
        if (half == 0) {
            const int nfull = bm + row;
            const int bq = nfull >> 10, n = nfull & 1023;
            const int o = (bq * HEADS + hglob) * NN + n;
            g_sdst[o] = dsum;
            g_f1[o] = __float2half_rn(__expf(ssum));
            g_f2[o] = __float2half_rn(__expf(ALPHA_LR * ssum));
        }
    }
}

// ---------------------------------------------------------------------------
// K3: fused masked softmax + PV (fp16) + ELU  -- R11 structure (best attn)
// block = (b, h, 128 i-rows); 8 warps each own m16 exclusively (warp n64).
// 64-j tiles: V (64x64 fp16, pitch 144B) + bitmask rows (8B/row) staged via
// 3-buffer prefetch-2 cp.async pipeline with ONE sync per tile (stage issued
// after the barrier; reuse distance 3 makes this safe).
// p = max(E1*F1, E2*F2) * mkexp-expanded bitmask. Denominator via ones-MMA.
// smem: 3 x (V 9216 | mask 1024) = 30720; F tables 4096.
// ---------------------------------------------------------------------------
#define AB_SZ 10240
#define AT_F (3 * AB_SZ)
#define ATTN_SMEM (AT_F + 4096)
#define NTILE (NN / 64)

__global__ __launch_bounds__(256, 4) void attn_mma(float* __restrict__ out)
{
    extern __shared__ char sp[];
    const uint32_t sb = smem_u32(sp);
    const int b = blockIdx.z, h = blockIdx.y;
    const int i0 = blockIdx.x * 128;
    const int tid = threadIdx.x;
    const int w = tid >> 5, lane = tid & 31;
    const int bh = b * HEADS + h;

    auto stageV = [&](int jt, int buf) {
        const uint32_t bb = sb + buf * AB_SZ;
        int k = tid >> 3, c = tid & 7;
#pragma unroll
        for (int s = 0; s < 2; s++) {
            int row = s * 32 + k;
            size_t src = (size_t)(b * NN + jt * 64 + row) * FOUT + h * DH + c * 8;
            cp16(bb + row * 144 + c * 16, &g_hh[src]);
        }
        if (tid < 128)
            cp8(bb + 9216 + tid * 8,
                &g_adjbits[(size_t)(b * NN + i0 + tid) * (NN / 32) + jt * 2]);
    };

    const int r = lane >> 2;
    const float sd0 = g_sdst[bh * NN + i0 + w * 16 + r];
    const float sd1 = g_sdst[bh * NN + i0 + w * 16 + r + 8];
    const __half2 E10 = __half2half2(__float2half_rn(__expf(sd0)));
    const __half2 E20 = __half2half2(__float2half_rn(__expf(ALPHA_LR * sd0)));
    const __half2 E11 = __half2half2(__float2half_rn(__expf(sd1)));
    const __half2 E21 = __half2half2(__float2half_rn(__expf(ALPHA_LR * sd1)));

    // group 0: F tables (2KB each) + V/mask tile 0 ; group 1: tile 1
    if (tid < 128) cp16(sb + AT_F + tid * 16, &g_f1[bh * NN + tid * 8]);
    else cp16(sb + AT_F + 2048 + (tid - 128) * 16, &g_f2[bh * NN + (tid - 128) * 8]);
    stageV(0, 0); CP_COMMIT();
    stageV(1, 1); CP_COMMIT();

    float acc[8][4];
#pragma unroll
    for (int i = 0; i < 8; i++)
#pragma unroll
        for (int q = 0; q < 4; q++) acc[i][q] = 0.f;
    float accd[4] = {0.f, 0.f, 0.f, 0.f};

    const char* spF = sp + AT_F;
    const int cq = (lane & 3) * 2;

#pragma unroll 1
    for (int jt = 0; jt < NTILE; jt++) {
        const int buf = jt % 3;
        if (jt + 1 < NTILE) CP_WAIT(1);
        else CP_WAIT(0);
        __syncthreads();
        if (jt + 2 < NTILE) { stageV(jt + 2, (jt + 2) % 3); CP_COMMIT(); }

        const uint32_t bb = sb + buf * AB_SZ;
        const uint2 mrow0 = *(const uint2*)(sp + buf * AB_SZ + 9216 +
                                            (w * 16 + r) * 8);
        const uint2 mrow1 = *(const uint2*)(sp + buf * AB_SZ + 9216 +
                                            (w * 16 + r + 8) * 8);
#pragma unroll
        for (int kc = 0; kc < 4; kc++) {
            const uint32_t w0 = (kc < 2) ? mrow0.x : mrow0.y;
            const uint32_t w1 = (kc < 2) ? mrow1.x : mrow1.y;
            const int sh = (kc & 1) * 16 + cq;
            const int jo = jt * 128 + kc * 32 + cq * 2;   // bytes into F tables
            uint32_t f1A = *(const uint32_t*)(spF + jo);
            uint32_t f1B = *(const uint32_t*)(spF + jo + 16);
            uint32_t f2A = *(const uint32_t*)(spF + 2048 + jo);
            uint32_t f2B = *(const uint32_t*)(spF + 2048 + jo + 16);
            uint32_t ah[4];
            ah[0] = ppair(f1A, f2A, E10, E20, mkexp(w0, sh));
            ah[1] = ppair(f1A, f2A, E11, E21, mkexp(w1, sh));
            ah[2] = ppair(f1B, f2B, E10, E20, mkexp(w0, sh + 8));
            ah[3] = ppair(f1B, f2B, E11, E21, mkexp(w1, sh + 8));

            // denominator: row sums via all-ones B fragment
            mma16816h(accd, ah, ONESH2, ONESH2);

            const int krow = kc * 16 + (lane & 15);
#pragma unroll
            for (int nt2 = 0; nt2 < 4; nt2++) {
                int col = nt2 * 16 + (lane >> 4) * 8;
                uint32_t bh4[4];
                ldsm_x4_t(bh4, bb + (krow * 144 + col * 2));
                mma16816h(acc[nt2 * 2],     ah, bh4[0], bh4[1]);
                mma16816h(acc[nt2 * 2 + 1], ah, bh4[2], bh4[3]);
            }
        }
    }

    const float inv0 = 1.f / accd[0];
    const float inv1 = 1.f / accd[2];

    // epilogue: normalize, ELU, store
    const size_t row0 = (size_t)(b * NN + i0 + w * 16 + r);
    const size_t row1 = row0 + 8;
#pragma unroll
    for (int nt = 0; nt < 8; nt++) {
        int col = h * DH + nt * 8 + cq;
        float o0 = acc[nt][0] * inv0; o0 = (o0 > 0.f) ? o0 : expm1f(o0);
        float o1 = acc[nt][1] * inv0; o1 = (o1 > 0.f) ? o1 : expm1f(o1);
        float o2 = acc[nt][2] * inv1; o2 = (o2 > 0.f) ? o2 : expm1f(o2);
        float o3 = acc[nt][3] * inv1; o3 = (o3 > 0.f) ? o3 : expm1f(o3);
        *(float2*)&out[row0 * FOUT + col] = make_float2(o0, o1);
        *(float2*)&out[row1 * FOUT + col] = make_float2(o2, o3);
    }
}

// ---------------------------------------------------------------------------
extern "C" void kernel_launch(void* const* d_in, const int* in_sizes, int n_in,
                              void* d_out, int out_size)
{
    const float* x   = (const float*)d_in[0];   // (8,1024,512)
    const int*   adj = (const int*)d_in[1];     // (8,1024,1024)
    const float* Ww  = (const float*)d_in[2];   // (512,512)
    const float* Wb  = (const float*)d_in[3];   // (512,)
    const float* att = (const float*)d_in[4];   // (8,128)
    float* out = (float*)d_out;                 // (8,1024,512)

    cudaFuncSetAttribute(gemm_mma, cudaFuncAttributeMaxDynamicSharedMemorySize,
                         GEMM_SMEM);
    cudaFuncSetAttribute(attn_mma, cudaFuncAttributeMaxDynamicSharedMemorySize,
                         ATTN_SMEM);

    const int nconv = BATCH * NN * FIN + FIN * FOUT;
    conv_xw<<<(nconv + 255) / 256, 256>>>(x, Ww);
    adj_pack<<<(BATCH * NN * NN) / 256, 256>>>(adj);
    gemm_mma<<<dim3(HEADS, (BATCH * NN) / 128), 256, GEMM_SMEM>>>(Wb, att);
    attn_mma<<<dim3(NN / 128, HEADS, BATCH), 256, ATTN_SMEM>>>(out);
}

// round 16
// speedup vs baseline: 1.1083x; 1.0216x over previous
#include <cuda_runtime.h>
#include <cuda_bf16.h>
#include <cuda_fp16.h>
#include <math.h>
#include <stdint.h>

// Problem constants: B=8, N=1024, Fin=512, Fout=512, H=8, dh=64
#define BATCH 8
#define NN    1024
#define FIN   512
#define FOUT  512
#define HEADS 8
#define DH    64
#define ALPHA_LR 0.2f

// ---------------- device scratch ----------------
__device__ __nv_bfloat16 g_xh[BATCH * NN * FIN];
__device__ __nv_bfloat16 g_xl[BATCH * NN * FIN];
__device__ __nv_bfloat16 g_wh[FIN * FOUT];
__device__ __nv_bfloat16 g_wl[FIN * FOUT];
__device__ __half        g_hh[BATCH * NN * FOUT];    // h (fp16)
__device__ float         g_sdst[BATCH * HEADS * NN];
__device__ __half        g_f1[BATCH * HEADS * NN];   // exp(ss) fp16
__device__ __half        g_f2[BATCH * HEADS * NN];   // exp(0.2*ss) fp16
__device__ unsigned      g_adjbits[BATCH * NN * (NN / 32)];

// ---------------- PTX helpers ----------------
static __device__ __forceinline__ uint32_t smem_u32(const void* p) {
    return (uint32_t)__cvta_generic_to_shared(p);
}
static __device__ __forceinline__ void ldsm_x4(uint32_t* r, uint32_t a) {
    asm volatile("ldmatrix.sync.aligned.m8n8.x4.shared.b16 {%0,%1,%2,%3}, [%4];"
        : "=r"(r[0]), "=r"(r[1]), "=r"(r[2]), "=r"(r[3]) : "r"(a));
}
static __device__ __forceinline__ void ldsm_x4_t(uint32_t* r, uint32_t a) {
    asm volatile("ldmatrix.sync.aligned.m8n8.x4.trans.shared.b16 {%0,%1,%2,%3}, [%4];"
        : "=r"(r[0]), "=r"(r[1]), "=r"(r[2]), "=r"(r[3]) : "r"(a));
}
// bf16 MMA (GEMM)
static __device__ __forceinline__ void mma16816(float* d, const uint32_t* a,
                                                uint32_t b0, uint32_t b1) {
    asm volatile(
        "mma.sync.aligned.m16n8k16.row.col.f32.bf16.bf16.f32 "
        "{%0,%1,%2,%3}, {%4,%5,%6,%7}, {%8,%9}, {%0,%1,%2,%3};"
        : "+f"(d[0]), "+f"(d[1]), "+f"(d[2]), "+f"(d[3])
        : "r"(a[0]), "r"(a[1]), "r"(a[2]), "r"(a[3]), "r"(b0), "r"(b1));
}
// fp16 MMA (attention P*V)
static __device__ __forceinline__ void mma16816h(float* d, const uint32_t* a,
                                                 uint32_t b0, uint32_t b1) {
    asm volatile(
        "mma.sync.aligned.m16n8k16.row.col.f32.f16.f16.f32 "
        "{%0,%1,%2,%3}, {%4,%5,%6,%7}, {%8,%9}, {%0,%1,%2,%3};"
        : "+f"(d[0]), "+f"(d[1]), "+f"(d[2]), "+f"(d[3])
        : "r"(a[0]), "r"(a[1]), "r"(a[2]), "r"(a[3]), "r"(b0), "r"(b1));
}
static __device__ __forceinline__ void cp16(uint32_t dst, const void* src) {
    asm volatile("cp.async.cg.shared.global [%0], [%1], 16;"
        :: "r"(dst), "l"(src) : "memory");
}
static __device__ __forceinline__ void cp8(uint32_t dst, const void* src) {
    asm volatile("cp.async.ca.shared.global [%0], [%1], 8;"
        :: "r"(dst), "l"(src) : "memory");
}
#define CP_COMMIT() asm volatile("cp.async.commit_group;" ::: "memory")
#define CP_WAIT(n)  asm volatile("cp.async.wait_group %0;" :: "n"(n) : "memory")

// expand bits (sh, sh+1) of w to packed fp16 {b0?1:0, b1?1:0}
static __device__ __forceinline__ uint32_t mkexp(uint32_t w, int sh) {
    uint32_t t = w >> sh;
    return (t & 1u) * 0x3C00u + (t & 2u) * 0x1E000000u;
}
// packed p-pair: p = max(E1*F1, E2*F2) * mask   (exp(leakyrelu) identity)
static __device__ __forceinline__ uint32_t ppair(uint32_t f1p, uint32_t f2p,
                                                 __half2 E1, __half2 E2,
                                                 uint32_t mk) {
    __half2 a = __hmul2(E1, *(__half2*)&f1p);
    __half2 b = __hmul2(E2, *(__half2*)&f2p);
    __half2 p = __hmul2(__hmax2(a, b), *(__half2*)&mk);
    return *(uint32_t*)&p;
}
#define ONESH2 0x3C003C00u

// ---------------------------------------------------------------------------
// C0: split X and W into bf16 hi/lo
// ---------------------------------------------------------------------------
__global__ __launch_bounds__(256) void conv_xw(const float* __restrict__ X,
                                               const float* __restrict__ W)
{
    int idx = blockIdx.x * 256 + threadIdx.x;
    const int NX = BATCH * NN * FIN;
    if (idx < NX) {
        float v = X[idx];
        __nv_bfloat16 hi = __float2bfloat16_rn(v);
        g_xh[idx] = hi;
        g_xl[idx] = __float2bfloat16_rn(v - __bfloat162float(hi));
    } else {
        int wi = idx - NX;
        if (wi < FIN * FOUT) {
            float v = W[wi];
            __nv_bfloat16 hi = __float2bfloat16_rn(v);
            g_wh[wi] = hi;
            g_wl[wi] = __float2bfloat16_rn(v - __bfloat162float(hi));
        }
    }
}

// ---------------------------------------------------------------------------
// C1: pack adjacency to bitmask (plain bit order, matches mkexp)
// ---------------------------------------------------------------------------
__global__ __launch_bounds__(256) void adj_pack(const int* __restrict__ adj)
{
    int e = blockIdx.x * 256 + threadIdx.x;
    unsigned m = __ballot_sync(0xffffffffu, adj[e] > 0);
    if ((threadIdx.x & 31) == 0) g_adjbits[e >> 5] = m;
}

// ---------------------------------------------------------------------------
// K1: split-bf16 MMA GEMM  h = X @ W + b   (3 terms)  -- R12 version (best)
// block tile 128m x 64n (one head wide), 8 warps 4m x 2n (warp m32 x n32).
// k-chunks of 32, 2-buffer prefetch-1 cp.async pipeline.
// A tiles XOR-swizzled (pitch 64B) -> smem 51.2KB -> occupancy 4, single wave.
// ---------------------------------------------------------------------------
#define GB_SZ 25600
#define GM_ATT (2 * GB_SZ)
#define GEMM_SMEM (GM_ATT + 512)
#define G_NCHUNK (FIN / 32)

__global__ __launch_bounds__(256, 4) void gemm_mma(const float* __restrict__ bias,
                                                   const float* __restrict__ att)
{
    extern __shared__ char sp[];
    const uint32_t sb = smem_u32(sp);
    const int tid = threadIdx.x;
    const int w = tid >> 5, lane = tid & 31;
    const int wm = w & 3, wn = w >> 2;          // 4m x 2n warps
    const int bm = blockIdx.y * 128;
    const int hglob = blockIdx.x;               // one head per block
    const int bn = hglob * 64;

    float* sAtt = (float*)(sp + GM_ATT);
    if (tid < 128) sAtt[tid] = att[hglob * 128 + tid];

    auto stage = [&](int c, int buf) {
        const uint32_t bb = sb + buf * GB_SZ;
#pragma unroll
        for (int s = 0; s < 2; s++) {
            int u = tid * 2 + s;
            int row = u >> 2, q = u & 3;
            int swq = q ^ ((row >> 1) & 3);
            size_t asrc = (size_t)(bm + row) * FIN + c * 32 + q * 8;
            cp16(bb + row * 64 + swq * 16, &g_xh[asrc]);
            cp16(bb + 8192 + row * 64 + swq * 16, &g_xl[asrc]);
        }
        int kr = tid >> 3, c2 = tid & 7;
        size_t bsrc = (size_t)(c * 32 + kr) * FOUT + bn + c2 * 8;
        cp16(bb + 16384 + kr * 144 + c2 * 16, &g_wh[bsrc]);
        cp16(bb + 16384 + 4608 + kr * 144 + c2 * 16, &g_wl[bsrc]);
    };

    float acc[2][4][4];
#pragma unroll
    for (int i = 0; i < 2; i++)
#pragma unroll
        for (int j = 0; j < 4; j++)
#pragma unroll
            for (int r = 0; r < 4; r++) acc[i][j][r] = 0.f;

    stage(0, 0); CP_COMMIT();

#pragma unroll 1
    for (int c = 0; c < G_NCHUNK; c++) {
        const int buf = c & 1;
        if (c + 1 < G_NCHUNK) { stage(c + 1, buf ^ 1); CP_COMMIT(); CP_WAIT(1); }
        else CP_WAIT(0);
        __syncthreads();

        const uint32_t bb = sb + buf * GB_SZ;
#pragma unroll
        for (int kc = 0; kc < 2; kc++) {
            uint32_t ah[2][4], al[2][4];
#pragma unroll
            for (int mt = 0; mt < 2; mt++) {
                int mrow = wm * 32 + mt * 16 + (lane & 15);
                int cch = kc * 2 + (lane >> 4);
                uint32_t ao = mrow * 64 + ((cch ^ ((mrow >> 1) & 3)) * 16);
                ldsm_x4(ah[mt], bb + ao);
                ldsm_x4(al[mt], bb + 8192 + ao);
            }
            const int krow = kc * 16 + (lane & 15);
#pragma unroll
            for (int p = 0; p < 2; p++) {
                int col = wn * 32 + p * 16 + (lane >> 4) * 8;
                uint32_t bo = krow * 144 + col * 2;
                uint32_t bh4[4], bl4[4];
                ldsm_x4_t(bh4, bb + 16384 + bo);
                ldsm_x4_t(bl4, bb + 16384 + 4608 + bo);
#pragma unroll
                for (int mt = 0; mt < 2; mt++) {
                    mma16816(acc[mt][2 * p],     ah[mt], bh4[0], bh4[1]);
                    mma16816(acc[mt][2 * p],     ah[mt], bl4[0], bl4[1]);
                    mma16816(acc[mt][2 * p],     al[mt], bh4[0], bh4[1]);
                    mma16816(acc[mt][2 * p + 1], ah[mt], bh4[2], bh4[3]);
                    mma16816(acc[mt][2 * p + 1], ah[mt], bl4[2], bl4[3]);
                    mma16816(acc[mt][2 * p + 1], al[mt], bh4[2], bh4[3]);
                }
            }
        }
        __syncthreads();
    }

    // -------- epilogue: bias, g_hh (fp16), dt stash --------
    float* dt = (float*)sp;                      // 128 x 65 fp32 (bufs dead)
    const int g = lane >> 2, t = lane & 3;
#pragma unroll
    for (int mt = 0; mt < 2; mt++) {
        const int r0 = wm * 32 + mt * 16 + g;
        const int r1 = r0 + 8;
#pragma unroll
        for (int nt = 0; nt < 4; nt++) {
            int colL = wn * 32 + nt * 8 + 2 * t;
            float2 bv = *(const float2*)&bias[bn + colL];
            float c0 = acc[mt][nt][0] + bv.x;
            float c1 = acc[mt][nt][1] + bv.y;
            float c2 = acc[mt][nt][2] + bv.x;
            float c3 = acc[mt][nt][3] + bv.y;
            dt[r0 * 65 + colL] = c0; dt[r0 * 65 + colL + 1] = c1;
            dt[r1 * 65 + colL] = c2; dt[r1 * 65 + colL + 1] = c3;
            size_t d0 = (size_t)(bm + r0) * FOUT + bn + colL;
            size_t d1 = (size_t)(bm + r1) * FOUT + bn + colL;
            *(__half2*)&g_hh[d0] =
                __halves2half2(__float2half_rn(c0), __float2half_rn(c1));
            *(__half2*)&g_hh[d1] =
                __halves2half2(__float2half_rn(c2), __float2half_rn(c3));
        }
    }
    __syncthreads();

    // -------- fused scores: sdst fp32 + factorized F1/F2 fp16 --------
    {
        const int row = tid >> 1, half = tid & 1;
        float ssum = 0.f, dsum = 0.f;
#pragma unroll 8
        for (int d = half * 32; d < half * 32 + 32; d++) {
            float v = dt[row * 65 + d];
            ssum = fmaf(v, sAtt[d], ssum);
            dsum = fmaf(v, sAtt[64 + d], dsum);
        }
        ssum += __shfl_xor_sync(0xffffffffu, ssum, 1);
        dsum += __shfl_xor_sync(0xffffffffu, dsum, 1);
        if (half == 0) {
            const int nfull = bm + row;
            const int bq = nfull >> 10, n = nfull & 1023;
            const int o = (bq * HEADS + hglob) * NN + n;
            g_sdst[o] = dsum;
            g_f1[o] = __float2half_rn(__expf(ssum));
            g_f2[o] = __float2half_rn(__expf(ALPHA_LR * ssum));
        }
    }
}

// ---------------------------------------------------------------------------
// K3: fused masked softmax + PV (fp16) + ELU  -- exact R11 structure (best)
// block = (b, h, 128 i-rows); 8 warps each own m16 exclusively (warp n64).
// 64-j tiles: V (64x64 fp16, pitch 144B) + bitmask rows (8B/row) staged via
// 2-buffer prefetch-1 cp.async (stage issued BEFORE the wait/barrier).
// p = max(E1*F1, E2*F2) * mkexp-expanded bitmask. Denominator via ones-MMA.
// smem per buf: V 9216 | mask 1024 = 10240, x2; F tables 4096.
// ---------------------------------------------------------------------------
#define AB_SZ 10240
#define AT_F (2 * AB_SZ)
#define ATTN_SMEM (AT_F + 4096)

__global__ __launch_bounds__(256, 4) void attn_mma(float* __restrict__ out)
{
    extern __shared__ char sp[];
    const uint32_t sb = smem_u32(sp);
    const int b = blockIdx.z, h = blockIdx.y;
    const int i0 = blockIdx.x * 128;
    const int tid = threadIdx.x;
    const int w = tid >> 5, lane = tid & 31;
    const int bh = b * HEADS + h;

    auto stageV = [&](int jt, int buf) {
        const uint32_t bb = sb + buf * AB_SZ;
        int k = tid >> 3, c = tid & 7;
#pragma unroll
        for (int s = 0; s < 2; s++) {
            int row = s * 32 + k;
            size_t src = (size_t)(b * NN + jt * 64 + row) * FOUT + h * DH + c * 8;
            cp16(bb + row * 144 + c * 16, &g_hh[src]);
        }
        if (tid < 128)
            cp8(bb + 9216 + tid * 8,
                &g_adjbits[(size_t)(b * NN + i0 + tid) * (NN / 32) + jt * 2]);
    };

    const int r = lane >> 2;
    const float sd0 = g_sdst[bh * NN + i0 + w * 16 + r];
    const float sd1 = g_sdst[bh * NN + i0 + w * 16 + r + 8];
    const __half2 E10 = __half2half2(__float2half_rn(__expf(sd0)));
    const __half2 E20 = __half2half2(__float2half_rn(__expf(ALPHA_LR * sd0)));
    const __half2 E11 = __half2half2(__float2half_rn(__expf(sd1)));
    const __half2 E21 = __half2half2(__float2half_rn(__expf(ALPHA_LR * sd1)));

    // group 0: F tables (2KB each) + V/mask tile 0
    if (tid < 128) cp16(sb + AT_F + tid * 16, &g_f1[bh * NN + tid * 8]);
    else cp16(sb + AT_F + 2048 + (tid - 128) * 16, &g_f2[bh * NN + (tid - 128) * 8]);
    stageV(0, 0); CP_COMMIT();

    float acc[8][4];
#pragma unroll
    for (int i = 0; i < 8; i++)
#pragma unroll
        for (int q = 0; q < 4; q++) acc[i][q] = 0.f;
    float accd[4] = {0.f, 0.f, 0.f, 0.f};

    const char* spF = sp + AT_F;
    const int cq = (lane & 3) * 2;

#pragma unroll 1
    for (int jt = 0; jt < NN / 64; jt++) {
        const int buf = jt & 1;
        if (jt + 1 < NN / 64) { stageV(jt + 1, buf ^ 1); CP_COMMIT(); CP_WAIT(1); }
        else CP_WAIT(0);
        __syncthreads();

        const uint32_t bb = sb + buf * AB_SZ;
        const uint2 mrow0 = *(const uint2*)(sp + buf * AB_SZ + 9216 +
                                            (w * 16 + r) * 8);
        const uint2 mrow1 = *(const uint2*)(sp + buf * AB_SZ + 9216 +
                                            (w * 16 + r + 8) * 8);
#pragma unroll
        for (int kc = 0; kc < 4; kc++) {
            const uint32_t w0 = (kc < 2) ? mrow0.x : mrow0.y;
            const uint32_t w1 = (kc < 2) ? mrow1.x : mrow1.y;
            const int sh = (kc & 1) * 16 + cq;
            const int jo = jt * 128 + kc * 32 + cq * 2;   // bytes into F tables
            uint32_t f1A = *(const uint32_t*)(spF + jo);
            uint32_t f1B = *(const uint32_t*)(spF + jo + 16);
            uint32_t f2A = *(const uint32_t*)(spF + 2048 + jo);
            uint32_t f2B = *(const uint32_t*)(spF + 2048 + jo + 16);
            uint32_t ah[4];
            ah[0] = ppair(f1A, f2A, E10, E20, mkexp(w0, sh));
            ah[1] = ppair(f1A, f2A, E11, E21, mkexp(w1, sh));
            ah[2] = ppair(f1B, f2B, E10, E20, mkexp(w0, sh + 8));
            ah[3] = ppair(f1B, f2B, E11, E21, mkexp(w1, sh + 8));

            // denominator: row sums via all-ones B fragment
            mma16816h(accd, ah, ONESH2, ONESH2);

            const int krow = kc * 16 + (lane & 15);
#pragma unroll
            for (int nt2 = 0; nt2 < 4; nt2++) {
                int col = nt2 * 16 + (lane >> 4) * 8;
                uint32_t bh4[4];
                ldsm_x4_t(bh4, bb + (krow * 144 + col * 2));
                mma16816h(acc[nt2 * 2],     ah, bh4[0], bh4[1]);
                mma16816h(acc[nt2 * 2 + 1], ah, bh4[2], bh4[3]);
            }
        }
        __syncthreads();
    }

    const float inv0 = 1.f / accd[0];
    const float inv1 = 1.f / accd[2];

    // epilogue: normalize, ELU, store
    const size_t row0 = (size_t)(b * NN + i0 + w * 16 + r);
    const size_t row1 = row0 + 8;
#pragma unroll
    for (int nt = 0; nt < 8; nt++) {
        int col = h * DH + nt * 8 + cq;
        float o0 = acc[nt][0] * inv0; o0 = (o0 > 0.f) ? o0 : expm1f(o0);
        float o1 = acc[nt][1] * inv0; o1 = (o1 > 0.f) ? o1 : expm1f(o1);
        float o2 = acc[nt][2] * inv1; o2 = (o2 > 0.f) ? o2 : expm1f(o2);
        float o3 = acc[nt][3] * inv1; o3 = (o3 > 0.f) ? o3 : expm1f(o3);
        *(float2*)&out[row0 * FOUT + col] = make_float2(o0, o1);
        *(float2*)&out[row1 * FOUT + col] = make_float2(o2, o3);
    }
}

// ---------------------------------------------------------------------------
extern "C" void kernel_launch(void* const* d_in, const int* in_sizes, int n_in,
                              void* d_out, int out_size)
{
    const float* x   = (const float*)d_in[0];   // (8,1024,512)
    const int*   adj = (const int*)d_in[1];     // (8,1024,1024)
    const float* Ww  = (const float*)d_in[2];   // (512,512)
    const float* Wb  = (const float*)d_in[3];   // (512,)
    const float* att = (const float*)d_in[4];   // (8,128)
    float* out = (float*)d_out;                 // (8,1024,512)

    cudaFuncSetAttribute(gemm_mma, cudaFuncAttributeMaxDynamicSharedMemorySize,
                         GEMM_SMEM);
    cudaFuncSetAttribute(attn_mma, cudaFuncAttributeMaxDynamicSharedMemorySize,
                         ATTN_SMEM);

    const int nconv = BATCH * NN * FIN + FIN * FOUT;
    conv_xw<<<(nconv + 255) / 256, 256>>>(x, Ww);
    adj_pack<<<(BATCH * NN * NN) / 256, 256>>>(adj);
    gemm_mma<<<dim3(HEADS, (BATCH * NN) / 128), 256, GEMM_SMEM>>>(Wb, att);
    attn_mma<<<dim3(NN / 128, HEADS, BATCH), 256, ATTN_SMEM>>>(out);
}